// round 8
// baseline (speedup 1.0000x reference)
#include <cuda_runtime.h>
#include <cuda_bf16.h>
#include <math.h>
#include <stdint.h>

#define NT 8192
#define DM 1024
#define FF 4096
#define NE 8
#define TOTAL_ROWS (NT * 2)

// packed-smem geometry in uint4 units: each row = 8 data uint4 + 1 pad = 9
#define TROW 9
#define HDR4 128                        // 2048 B header
#define ATILE4 (128 * TROW)             // 1152 uint4
#define BTILE4 (128 * TROW)             // 1152 uint4
#define STAGE4 (ATILE4 + BTILE4)        // 2304 uint4
#define SMEM4  (HDR4 + 2 * STAGE4)      // 4736 uint4
#define SMEM_BYTES (SMEM4 * 16)         // 75776 B

// ---------------- scratch (device globals; no runtime alloc) ----------------
__device__ int   g_cnt[NE];
__device__ int   g_off[NE];
__device__ int   g_tok[NE * NT];
__device__ float g_w  [NE * NT];
// padded by 128 rows so OOB-tile A loads in GEMM2 stay in-bounds
__device__ __align__(16) float g_h[(size_t)(TOTAL_ROWS + 128) * FF];

// ---------------- mma.sync (validated in R7) ----------------
__device__ __forceinline__ void mma_bf16(float (&d)[4], const uint32_t (&a)[4],
                                         uint32_t b0, uint32_t b1) {
    asm volatile("mma.sync.aligned.m16n8k16.row.col.f32.bf16.bf16.f32 "
        "{%0,%1,%2,%3}, {%4,%5,%6,%7}, {%8,%9}, {%0,%1,%2,%3};"
        : "+f"(d[0]), "+f"(d[1]), "+f"(d[2]), "+f"(d[3])
        : "r"(a[0]), "r"(a[1]), "r"(a[2]), "r"(a[3]), "r"(b0), "r"(b1));
}

// split two fp32 into packed bf16x2 hi and lo (v = hi + lo, ~16-bit mantissa)
__device__ __forceinline__ void split2(float v0, float v1, uint32_t& hi, uint32_t& lo) {
    __nv_bfloat162 h = __floats2bfloat162_rn(v0, v1);   // .x = v0 (low half)
    float r0 = v0 - __bfloat162float(h.x);
    float r1 = v1 - __bfloat162float(h.y);
    __nv_bfloat162 l = __floats2bfloat162_rn(r0, r1);
    hi = *reinterpret_cast<uint32_t*>(&h);
    lo = *reinterpret_cast<uint32_t*>(&l);
}

// ---------------- zero counts + output ----------------
__global__ void zero_kernel(float* __restrict__ out) {
    int i = blockIdx.x * blockDim.x + threadIdx.x;
    if (i < NE) g_cnt[i] = 0;
    float4* o4 = reinterpret_cast<float4*>(out);
    if (i < NT * DM / 4) o4[i] = make_float4(0.f, 0.f, 0.f, 0.f);
}

// ---------------- gate (validated in R1) ----------------
__global__ void gate_kernel(const float* __restrict__ x,
                            const float* __restrict__ Wg,
                            const float* __restrict__ bg) {
    int gtid = blockIdx.x * blockDim.x + threadIdx.x;
    int t = gtid >> 5, lane = gtid & 31;
    if (t >= NT) return;
    const float* xr = x + (size_t)t * DM;
    float acc[NE];
#pragma unroll
    for (int e = 0; e < NE; e++) acc[e] = 0.f;
    for (int k = lane; k < DM; k += 32) {
        float xv = xr[k];
        const float* wr = Wg + k * NE;
#pragma unroll
        for (int e = 0; e < NE; e++) acc[e] += xv * wr[e];
    }
#pragma unroll
    for (int s = 16; s > 0; s >>= 1)
#pragma unroll
        for (int e = 0; e < NE; e++) acc[e] += __shfl_xor_sync(0xffffffffu, acc[e], s);
    if (lane == 0) {
#pragma unroll
        for (int e = 0; e < NE; e++) acc[e] += bg[e];
        float mx = acc[0];
#pragma unroll
        for (int e = 1; e < NE; e++) mx = fmaxf(mx, acc[e]);
        float s = 0.f;
#pragma unroll
        for (int e = 0; e < NE; e++) { acc[e] = expf(acc[e] - mx); s += acc[e]; }
        float inv = 1.f / s;
#pragma unroll
        for (int e = 0; e < NE; e++) acc[e] *= inv;
        int i0 = 0;
#pragma unroll
        for (int e = 1; e < NE; e++) if (acc[e] > acc[i0]) i0 = e;
        int i1 = (i0 == 0) ? 1 : 0;
#pragma unroll
        for (int e = 0; e < NE; e++) if (e != i0 && acc[e] > acc[i1]) i1 = e;
        float s2 = acc[i0] + acc[i1] + 1e-9f;
        int p0 = atomicAdd(&g_cnt[i0], 1);
        g_tok[i0 * NT + p0] = t;  g_w[i0 * NT + p0] = acc[i0] / s2;
        int p1 = atomicAdd(&g_cnt[i1], 1);
        g_tok[i1 * NT + p1] = t;  g_w[i1 * NT + p1] = acc[i1] / s2;
    }
}

__global__ void offsets_kernel() {
    if (threadIdx.x == 0 && blockIdx.x == 0) {
        int s = 0;
#pragma unroll
        for (int e = 0; e < NE; e++) { g_off[e] = s; s += g_cnt[e]; }
    }
}

// ---- staging: pack 4 fp32 k-pairs (one half-row) into interleaved hi/lo words ----
// word layout within a row (32 words): group q=0..3: [4q]=hi(p=q) [4q+1]=hi(q+4)
// [4q+2]=lo(q) [4q+3]=lo(q+4).  This thread covers pairs p = khalf*4 + (0..3).
__device__ __forceinline__ void stage_halfrow(uint32_t* smw, uint32_t rowword,
                                              int khalf, float4 v0, float4 v1) {
    uint32_t h, l;
    split2(v0.x, v0.y, h, l);
    smw[rowword + 0 + khalf] = h;  smw[rowword + 2 + khalf] = l;
    split2(v0.z, v0.w, h, l);
    smw[rowword + 4 + khalf] = h;  smw[rowword + 6 + khalf] = l;
    split2(v1.x, v1.y, h, l);
    smw[rowword + 8 + khalf] = h;  smw[rowword + 10 + khalf] = l;
    split2(v1.z, v1.w, h, l);
    smw[rowword + 12 + khalf] = h; smw[rowword + 14 + khalf] = l;
}

// ---- inner compute on one k16 stage: 12 LDS.128 + 48 MMA per warp ----
__device__ __forceinline__ void compute_stage16(const uint4* __restrict__ A4,
                                                const uint4* __restrict__ B4,
                                                int wm, int wn, int lid,
                                                float (&acc)[2][8][4]) {
    const int qr = lid >> 2, q = lid & 3;
    uint32_t ah[2][4], al[2][4];
#pragma unroll
    for (int mf = 0; mf < 2; mf++) {
        uint4 U1 = A4[(wm + mf * 16 + qr) * TROW + q];
        uint4 U2 = A4[(wm + mf * 16 + qr + 8) * TROW + q];
        ah[mf][0] = U1.x; ah[mf][1] = U2.x; ah[mf][2] = U1.y; ah[mf][3] = U2.y;
        al[mf][0] = U1.z; al[mf][1] = U2.z; al[mf][2] = U1.w; al[mf][3] = U2.w;
    }
#pragma unroll
    for (int g = 0; g < 8; g++) {
        uint4 V = B4[(wn + g * 8 + qr) * TROW + q];
#pragma unroll
        for (int mf = 0; mf < 2; mf++) {
            mma_bf16(acc[mf][g], ah[mf], V.x, V.y);   // hi*hi
            mma_bf16(acc[mf][g], al[mf], V.x, V.y);   // lo*hi
            mma_bf16(acc[mf][g], ah[mf], V.z, V.w);   // hi*lo
        }
    }
}

// ================= GEMM1: h = gelu(x[tok] @ W1[:, n] + b1) =================
__global__ __launch_bounds__(256, 2) void ffn1_hmma(const float* __restrict__ x,
                                                    const float* __restrict__ W1,
                                                    const float* __restrict__ b1) {
    extern __shared__ uint4 sm4[];
    const int e = blockIdx.z;
    const int cnt = g_cnt[e];
    const int mbase = blockIdx.y * 128;
    if (mbase >= cnt) return;
    const int nbase = blockIdx.x * 128;

    const int tid = threadIdx.x, wid = tid >> 5, lid = tid & 31;
    const int wm = (wid & 3) * 32, wn = (wid >> 2) * 64;

    int*   stok  = reinterpret_cast<int*>(sm4);
    float* sbias = reinterpret_cast<float*>(sm4) + 128;
    uint32_t* smw = reinterpret_cast<uint32_t*>(sm4);

    if (tid < 128) {
        int mi = mbase + tid;
        stok[tid]  = (mi < cnt) ? g_tok[e * NT + mi] : g_tok[e * NT + mbase];
        sbias[tid] = b1[e * FF + nbase + tid];
    }
    __syncthreads();

    // staging maps
    const int am = tid >> 1, khalf = tid & 1;           // A: 2 thr/row, 8 k each
    const int kpr = tid >> 5, nq = tid & 31;            // B: row-pair 2kpr, 4 n each
    const float* arow  = x + (size_t)stok[am] * DM + khalf * 8;
    const float* brow0 = W1 + (size_t)e * DM * FF + (size_t)(2 * kpr) * FF + nbase + nq * 4;
    const float* brow1 = brow0 + FF;
    const uint32_t awbase = (uint32_t)((HDR4 + am * TROW) * 4 + 0);
    const int bslot = 4 * (kpr & 3) + (kpr >> 2);

    float acc[2][8][4];
#pragma unroll
    for (int i = 0; i < 2; i++)
#pragma unroll
        for (int j = 0; j < 8; j++)
#pragma unroll
            for (int k = 0; k < 4; k++) acc[i][j][k] = 0.f;

    float4 ax0 = *reinterpret_cast<const float4*>(arow);
    float4 ax1 = *reinterpret_cast<const float4*>(arow + 4);
    float4 bx0 = *reinterpret_cast<const float4*>(brow0);
    float4 bx1 = *reinterpret_cast<const float4*>(brow1);

    int buf = 0;
    for (int kt = 0; kt < DM; kt += 16) {
        // store prefetched regs into buffer `buf`
        {
            uint32_t aw = awbase + (uint32_t)(buf * STAGE4 * 4);
            stage_halfrow(smw, aw, khalf, ax0, ax1);
            uint32_t bwb = (uint32_t)((HDR4 + buf * STAGE4 + ATILE4) * 4);
            uint32_t h, l;
            split2(bx0.x, bx1.x, h, l);
            smw[bwb + (nq * 4 + 0) * (TROW * 4) + bslot] = h;
            smw[bwb + (nq * 4 + 0) * (TROW * 4) + bslot + 2] = l;
            split2(bx0.y, bx1.y, h, l);
            smw[bwb + (nq * 4 + 1) * (TROW * 4) + bslot] = h;
            smw[bwb + (nq * 4 + 1) * (TROW * 4) + bslot + 2] = l;
            split2(bx0.z, bx1.z, h, l);
            smw[bwb + (nq * 4 + 2) * (TROW * 4) + bslot] = h;
            smw[bwb + (nq * 4 + 2) * (TROW * 4) + bslot + 2] = l;
            split2(bx0.w, bx1.w, h, l);
            smw[bwb + (nq * 4 + 3) * (TROW * 4) + bslot] = h;
            smw[bwb + (nq * 4 + 3) * (TROW * 4) + bslot + 2] = l;
        }
        __syncthreads();
        if (kt + 16 < DM) {   // prefetch next stage while computing this one
            ax0 = *reinterpret_cast<const float4*>(arow + kt + 16);
            ax1 = *reinterpret_cast<const float4*>(arow + kt + 20);
            bx0 = *reinterpret_cast<const float4*>(brow0 + (size_t)(kt + 16) * FF);
            bx1 = *reinterpret_cast<const float4*>(brow1 + (size_t)(kt + 16) * FF);
        }
        compute_stage16(sm4 + HDR4 + buf * STAGE4,
                        sm4 + HDR4 + buf * STAGE4 + ATILE4, wm, wn, lid, acc);
        buf ^= 1;
    }

    // epilogue: bias + exact GELU -> fp32 h   (validated R7)
    const int hoff = g_off[e];
    const int qr = lid >> 2, c2 = (lid & 3) * 2;
#pragma unroll
    for (int mf = 0; mf < 2; mf++)
#pragma unroll
        for (int half = 0; half < 2; half++) {
            int m = mbase + wm + mf * 16 + qr + half * 8;
            if (m < cnt) {
                float* hr = g_h + (size_t)(hoff + m) * FF + nbase;
#pragma unroll
                for (int g = 0; g < 8; g++) {
                    int cl = wn + g * 8 + c2;
                    float v0 = acc[mf][g][half * 2]     + sbias[cl];
                    float v1 = acc[mf][g][half * 2 + 1] + sbias[cl + 1];
                    hr[cl]     = 0.5f * v0 * (1.f + erff(v0 * 0.70710678118654752f));
                    hr[cl + 1] = 0.5f * v1 * (1.f + erff(v1 * 0.70710678118654752f));
                }
            }
        }
}

// ================= GEMM2: out[tok] += w * (h @ W2[:, n] + b2) =================
__global__ __launch_bounds__(256, 2) void ffn2_hmma(const float* __restrict__ W2,
                                                    const float* __restrict__ b2,
                                                    float* __restrict__ out) {
    extern __shared__ uint4 sm4[];
    const int e = blockIdx.z;
    const int cnt = g_cnt[e];
    const int mbase = blockIdx.y * 128;
    if (mbase >= cnt) return;
    const int nbase = blockIdx.x * 128;

    const int tid = threadIdx.x, wid = tid >> 5, lid = tid & 31;
    const int wm = (wid & 3) * 32, wn = (wid >> 2) * 64;

    int*   stok  = reinterpret_cast<int*>(sm4);
    float* sbias = reinterpret_cast<float*>(sm4) + 128;
    float* swt   = reinterpret_cast<float*>(sm4) + 256;
    uint32_t* smw = reinterpret_cast<uint32_t*>(sm4);

    if (tid < 128) {
        int mi = mbase + tid;
        bool v = mi < cnt;
        stok[tid]  = v ? g_tok[e * NT + mi] : 0;
        swt[tid]   = v ? g_w  [e * NT + mi] : 0.f;
        sbias[tid] = b2[e * DM + nbase + tid];
    }
    __syncthreads();

    const int hoff = g_off[e];
    const int am = tid >> 1, khalf = tid & 1;
    const int kpr = tid >> 5, nq = tid & 31;
    const float* arow  = g_h + (size_t)(hoff + mbase + am) * FF + khalf * 8;   // padded
    const float* brow0 = W2 + (size_t)e * FF * DM + (size_t)(2 * kpr) * DM + nbase + nq * 4;
    const float* brow1 = brow0 + DM;
    const uint32_t awbase = (uint32_t)((HDR4 + am * TROW) * 4);
    const int bslot = 4 * (kpr & 3) + (kpr >> 2);

    float acc[2][8][4];
#pragma unroll
    for (int i = 0; i < 2; i++)
#pragma unroll
        for (int j = 0; j < 8; j++)
#pragma unroll
            for (int k = 0; k < 4; k++) acc[i][j][k] = 0.f;

    float4 ax0 = *reinterpret_cast<const float4*>(arow);
    float4 ax1 = *reinterpret_cast<const float4*>(arow + 4);
    float4 bx0 = *reinterpret_cast<const float4*>(brow0);
    float4 bx1 = *reinterpret_cast<const float4*>(brow1);

    int buf = 0;
    for (int kt = 0; kt < FF; kt += 16) {
        {
            uint32_t aw = awbase + (uint32_t)(buf * STAGE4 * 4);
            stage_halfrow(smw, aw, khalf, ax0, ax1);
            uint32_t bwb = (uint32_t)((HDR4 + buf * STAGE4 + ATILE4) * 4);
            uint32_t h, l;
            split2(bx0.x, bx1.x, h, l);
            smw[bwb + (nq * 4 + 0) * (TROW * 4) + bslot] = h;
            smw[bwb + (nq * 4 + 0) * (TROW * 4) + bslot + 2] = l;
            split2(bx0.y, bx1.y, h, l);
            smw[bwb + (nq * 4 + 1) * (TROW * 4) + bslot] = h;
            smw[bwb + (nq * 4 + 1) * (TROW * 4) + bslot + 2] = l;
            split2(bx0.z, bx1.z, h, l);
            smw[bwb + (nq * 4 + 2) * (TROW * 4) + bslot] = h;
            smw[bwb + (nq * 4 + 2) * (TROW * 4) + bslot + 2] = l;
            split2(bx0.w, bx1.w, h, l);
            smw[bwb + (nq * 4 + 3) * (TROW * 4) + bslot] = h;
            smw[bwb + (nq * 4 + 3) * (TROW * 4) + bslot + 2] = l;
        }
        __syncthreads();
        if (kt + 16 < FF) {
            ax0 = *reinterpret_cast<const float4*>(arow + kt + 16);
            ax1 = *reinterpret_cast<const float4*>(arow + kt + 20);
            bx0 = *reinterpret_cast<const float4*>(brow0 + (size_t)(kt + 16) * DM);
            bx1 = *reinterpret_cast<const float4*>(brow1 + (size_t)(kt + 16) * DM);
        }
        compute_stage16(sm4 + HDR4 + buf * STAGE4,
                        sm4 + HDR4 + buf * STAGE4 + ATILE4, wm, wn, lid, acc);
        buf ^= 1;
    }

    // epilogue: bias + gate-weighted scatter (validated R7)
    const int qr = lid >> 2, c2 = (lid & 3) * 2;
#pragma unroll
    for (int mf = 0; mf < 2; mf++)
#pragma unroll
        for (int half = 0; half < 2; half++) {
            int mloc = wm + mf * 16 + qr + half * 8;
            int m = mbase + mloc;
            if (m < cnt) {
                int   tok = stok[mloc];
                float wv  = swt[mloc];
                float* orow = out + (size_t)tok * DM + nbase;
#pragma unroll
                for (int g = 0; g < 8; g++) {
                    int cl = wn + g * 8 + c2;
                    atomicAdd(&orow[cl],     wv * (acc[mf][g][half * 2]     + sbias[cl]));
                    atomicAdd(&orow[cl + 1], wv * (acc[mf][g][half * 2 + 1] + sbias[cl + 1]));
                }
            }
        }
}

// ---------------------------------------------------------------
extern "C" void kernel_launch(void* const* d_in, const int* in_sizes, int n_in,
                              void* d_out, int out_size) {
    const float* x  = (const float*)d_in[0];
    const float* Wg = (const float*)d_in[1];
    const float* bg = (const float*)d_in[2];
    const float* W1 = (const float*)d_in[3];
    const float* b1 = (const float*)d_in[4];
    const float* W2 = (const float*)d_in[5];
    const float* b2 = (const float*)d_in[6];
    float* out = (float*)d_out;

    cudaFuncSetAttribute(ffn1_hmma, cudaFuncAttributeMaxDynamicSharedMemorySize, SMEM_BYTES);
    cudaFuncSetAttribute(ffn2_hmma, cudaFuncAttributeMaxDynamicSharedMemorySize, SMEM_BYTES);

    zero_kernel<<<NT * DM / 4 / 256, 256>>>(out);
    gate_kernel<<<1024, 256>>>(x, Wg, bg);
    offsets_kernel<<<1, 32>>>();
    ffn1_hmma<<<dim3(FF / 128, NT / 128, NE), 256, SMEM_BYTES>>>(x, W1, b1);
    ffn2_hmma<<<dim3(DM / 128, NT / 128, NE), 256, SMEM_BYTES>>>(W2, b2, out);
}

// round 12
// speedup vs baseline: 1.4356x; 1.4356x over previous
#include <cuda_runtime.h>
#include <cuda_bf16.h>
#include <math.h>
#include <stdint.h>

#define NT 8192
#define DM 1024
#define FF 4096
#define NE 8
#define TOTAL_ROWS (NT * 2)

// smem geometry (floats): header 384, per stage: A [128][40] + B [32][132]
#define SA 40
#define SB 132
#define HDR 384
#define STAGEF (128 * SA + 32 * SB)            // 9344 floats per stage
#define SMEM_FLOATS (HDR + 2 * STAGEF)         // 19072 floats
#define SMEM_BYTES (SMEM_FLOATS * 4)           // 76288 B (needs opt-in)

// ---------------- scratch (device globals; no runtime alloc) ----------------
__device__ int   g_cnt[NE];
__device__ int   g_off[NE];
__device__ int   g_tok[NE * NT];
__device__ float g_w  [NE * NT];
// padded by 128 rows so OOB-tile A loads in GEMM2 stay in-bounds
__device__ __align__(16) float g_h[(size_t)(TOTAL_ROWS + 128) * FF];

// ---------------- mma.sync (validated R7) ----------------
__device__ __forceinline__ void mma_bf16(float (&d)[4], const uint32_t (&a)[4],
                                         uint32_t b0, uint32_t b1) {
    asm volatile("mma.sync.aligned.m16n8k16.row.col.f32.bf16.bf16.f32 "
        "{%0,%1,%2,%3}, {%4,%5,%6,%7}, {%8,%9}, {%0,%1,%2,%3};"
        : "+f"(d[0]), "+f"(d[1]), "+f"(d[2]), "+f"(d[3])
        : "r"(a[0]), "r"(a[1]), "r"(a[2]), "r"(a[3]), "r"(b0), "r"(b1));
}

// split two fp32 into packed bf16x2 hi and lo (v = hi + lo, ~16-bit mantissa)
__device__ __forceinline__ void split2(float v0, float v1, uint32_t& hi, uint32_t& lo) {
    __nv_bfloat162 h = __floats2bfloat162_rn(v0, v1);   // .x = v0 (low half)
    float r0 = v0 - __bfloat162float(h.x);
    float r1 = v1 - __bfloat162float(h.y);
    __nv_bfloat162 l = __floats2bfloat162_rn(r0, r1);
    hi = *reinterpret_cast<uint32_t*>(&h);
    lo = *reinterpret_cast<uint32_t*>(&l);
}

// ---------------- zero counts + output ----------------
__global__ void zero_kernel(float* __restrict__ out) {
    int i = blockIdx.x * blockDim.x + threadIdx.x;
    if (i < NE) g_cnt[i] = 0;
    float4* o4 = reinterpret_cast<float4*>(out);
    if (i < NT * DM / 4) o4[i] = make_float4(0.f, 0.f, 0.f, 0.f);
}

// ---------------- gate (validated R1) ----------------
__global__ void gate_kernel(const float* __restrict__ x,
                            const float* __restrict__ Wg,
                            const float* __restrict__ bg) {
    int gtid = blockIdx.x * blockDim.x + threadIdx.x;
    int t = gtid >> 5, lane = gtid & 31;
    if (t >= NT) return;
    const float* xr = x + (size_t)t * DM;
    float acc[NE];
#pragma unroll
    for (int e = 0; e < NE; e++) acc[e] = 0.f;
    for (int k = lane; k < DM; k += 32) {
        float xv = xr[k];
        const float* wr = Wg + k * NE;
#pragma unroll
        for (int e = 0; e < NE; e++) acc[e] += xv * wr[e];
    }
#pragma unroll
    for (int s = 16; s > 0; s >>= 1)
#pragma unroll
        for (int e = 0; e < NE; e++) acc[e] += __shfl_xor_sync(0xffffffffu, acc[e], s);
    if (lane == 0) {
#pragma unroll
        for (int e = 0; e < NE; e++) acc[e] += bg[e];
        float mx = acc[0];
#pragma unroll
        for (int e = 1; e < NE; e++) mx = fmaxf(mx, acc[e]);
        float s = 0.f;
#pragma unroll
        for (int e = 0; e < NE; e++) { acc[e] = expf(acc[e] - mx); s += acc[e]; }
        float inv = 1.f / s;
#pragma unroll
        for (int e = 0; e < NE; e++) acc[e] *= inv;
        int i0 = 0;
#pragma unroll
        for (int e = 1; e < NE; e++) if (acc[e] > acc[i0]) i0 = e;
        int i1 = (i0 == 0) ? 1 : 0;
#pragma unroll
        for (int e = 0; e < NE; e++) if (e != i0 && acc[e] > acc[i1]) i1 = e;
        float s2 = acc[i0] + acc[i1] + 1e-9f;
        int p0 = atomicAdd(&g_cnt[i0], 1);
        g_tok[i0 * NT + p0] = t;  g_w[i0 * NT + p0] = acc[i0] / s2;
        int p1 = atomicAdd(&g_cnt[i1], 1);
        g_tok[i1 * NT + p1] = t;  g_w[i1 * NT + p1] = acc[i1] / s2;
    }
}

__global__ void offsets_kernel() {
    if (threadIdx.x == 0 && blockIdx.x == 0) {
        int s = 0;
#pragma unroll
        for (int e = 0; e < NE; e++) { g_off[e] = s; s += g_cnt[e]; }
    }
}

// ---- shared compute: one k32 smem stage, on-the-fly split (validated R7) ----
__device__ __forceinline__ void compute_stage(const float* __restrict__ As,
                                              const float* __restrict__ Bs,
                                              int wm, int wn, int lid,
                                              float (&acc)[2][8][4]) {
    const int qr = lid >> 2;
    const int c2 = (lid & 3) * 2;
#pragma unroll
    for (int s = 0; s < 2; s++) {
        const int kk = s * 16 + c2;
        uint32_t ah[2][4], al[2][4];
#pragma unroll
        for (int mf = 0; mf < 2; mf++) {
            const int r = wm + mf * 16 + qr;
            float2 p0 = *reinterpret_cast<const float2*>(&As[r * SA + kk]);
            float2 p1 = *reinterpret_cast<const float2*>(&As[(r + 8) * SA + kk]);
            float2 p2 = *reinterpret_cast<const float2*>(&As[r * SA + kk + 8]);
            float2 p3 = *reinterpret_cast<const float2*>(&As[(r + 8) * SA + kk + 8]);
            split2(p0.x, p0.y, ah[mf][0], al[mf][0]);
            split2(p1.x, p1.y, ah[mf][1], al[mf][1]);
            split2(p2.x, p2.y, ah[mf][2], al[mf][2]);
            split2(p3.x, p3.y, ah[mf][3], al[mf][3]);
        }
#pragma unroll
        for (int g = 0; g < 8; g++) {
            const int n = wn + g * 8 + qr;
            float b00 = Bs[kk * SB + n];
            float b01 = Bs[(kk + 1) * SB + n];
            float b10 = Bs[(kk + 8) * SB + n];
            float b11 = Bs[(kk + 9) * SB + n];
            uint32_t bh0, bl0, bh1, bl1;
            split2(b00, b01, bh0, bl0);
            split2(b10, b11, bh1, bl1);
#pragma unroll
            for (int mf = 0; mf < 2; mf++) {
                mma_bf16(acc[mf][g], ah[mf], bh0, bh1);   // hi*hi
                mma_bf16(acc[mf][g], al[mf], bh0, bh1);   // lo*hi
                mma_bf16(acc[mf][g], ah[mf], bl0, bl1);   // hi*lo
            }
        }
    }
}

// ================= GEMM1: h = gelu(x[tok] @ W1[:, n] + b1) =================
__global__ __launch_bounds__(256, 2) void ffn1_hmma(const float* __restrict__ x,
                                                    const float* __restrict__ W1,
                                                    const float* __restrict__ b1) {
    extern __shared__ float sm[];
    const int e = blockIdx.z;
    const int cnt = g_cnt[e];
    const int mbase = blockIdx.y * 128;
    if (mbase >= cnt) return;
    const int nbase = blockIdx.x * 128;

    const int tid = threadIdx.x, wid = tid >> 5, lid = tid & 31;
    const int wm = (wid & 3) * 32, wn = (wid >> 2) * 64;

    int*   stok  = reinterpret_cast<int*>(sm);
    float* sbias = sm + 128;

    if (tid < 128) {
        int mi = mbase + tid;
        stok[tid]  = (mi < cnt) ? g_tok[e * NT + mi] : g_tok[e * NT + mbase];
        sbias[tid] = b1[e * FF + nbase + tid];
    }
    __syncthreads();

    const int am = tid >> 1, ak = (tid & 1) * 16;     // A: 2 thr/row, 16 k each
    const int bk = tid >> 3, bn = (tid & 7) * 16;     // B: 8 thr/row, 16 n each
    const float* xrow = x + (size_t)stok[am] * DM + ak;
    const float* wrow = W1 + (size_t)e * DM * FF + (size_t)bk * FF + nbase + bn;

    float acc[2][8][4];
#pragma unroll
    for (int i = 0; i < 2; i++)
#pragma unroll
        for (int j = 0; j < 8; j++)
#pragma unroll
            for (int k = 0; k < 4; k++) acc[i][j][k] = 0.f;

    float4 ra[4], rb[4];
#pragma unroll
    for (int j = 0; j < 4; j++) {
        ra[j] = *reinterpret_cast<const float4*>(xrow + j * 4);
        rb[j] = *reinterpret_cast<const float4*>(wrow + j * 4);
    }

    int buf = 0;
    for (int kt = 0; kt < DM; kt += 32) {
        float* As = sm + HDR + buf * STAGEF;
        float* Bs = As + 128 * SA;
#pragma unroll
        for (int j = 0; j < 4; j++) {
            *reinterpret_cast<float4*>(&As[am * SA + ak + j * 4]) = ra[j];
            *reinterpret_cast<float4*>(&Bs[bk * SB + bn + j * 4]) = rb[j];
        }
        __syncthreads();
        if (kt + 32 < DM) {   // prefetch next stage; latency overlaps compute
#pragma unroll
            for (int j = 0; j < 4; j++) {
                ra[j] = *reinterpret_cast<const float4*>(xrow + kt + 32 + j * 4);
                rb[j] = *reinterpret_cast<const float4*>(wrow + (size_t)(kt + 32) * FF + j * 4);
            }
        }
        compute_stage(As, Bs, wm, wn, lid, acc);
        buf ^= 1;   // next store goes to the other buffer: no second sync needed
    }

    // epilogue: bias + exact GELU -> fp32 h (validated R7)
    const int hoff = g_off[e];
    const int qr = lid >> 2, c2 = (lid & 3) * 2;
#pragma unroll
    for (int mf = 0; mf < 2; mf++)
#pragma unroll
        for (int half = 0; half < 2; half++) {
            int m = mbase + wm + mf * 16 + qr + half * 8;
            if (m < cnt) {
                float* hr = g_h + (size_t)(hoff + m) * FF + nbase;
#pragma unroll
                for (int g = 0; g < 8; g++) {
                    int cl = wn + g * 8 + c2;
                    float v0 = acc[mf][g][half * 2]     + sbias[cl];
                    float v1 = acc[mf][g][half * 2 + 1] + sbias[cl + 1];
                    hr[cl]     = 0.5f * v0 * (1.f + erff(v0 * 0.70710678118654752f));
                    hr[cl + 1] = 0.5f * v1 * (1.f + erff(v1 * 0.70710678118654752f));
                }
            }
        }
}

// ================= GEMM2: out[tok] += w * (h @ W2[:, n] + b2) =================
__global__ __launch_bounds__(256, 2) void ffn2_hmma(const float* __restrict__ W2,
                                                    const float* __restrict__ b2,
                                                    float* __restrict__ out) {
    extern __shared__ float sm[];
    const int e = blockIdx.z;
    const int cnt = g_cnt[e];
    const int mbase = blockIdx.y * 128;
    if (mbase >= cnt) return;
    const int nbase = blockIdx.x * 128;

    const int tid = threadIdx.x, wid = tid >> 5, lid = tid & 31;
    const int wm = (wid & 3) * 32, wn = (wid >> 2) * 64;

    int*   stok  = reinterpret_cast<int*>(sm);
    float* sbias = sm + 128;
    float* swt   = sm + 256;

    if (tid < 128) {
        int mi = mbase + tid;
        bool v = mi < cnt;
        stok[tid]  = v ? g_tok[e * NT + mi] : 0;
        swt[tid]   = v ? g_w  [e * NT + mi] : 0.f;
        sbias[tid] = b2[e * DM + nbase + tid];
    }
    __syncthreads();

    const int hoff = g_off[e];
    const int am = tid >> 1, ak = (tid & 1) * 16;
    const int bk = tid >> 3, bn = (tid & 7) * 16;
    const float* arow = g_h + (size_t)(hoff + mbase + am) * FF + ak;   // padded scratch
    const float* wrow = W2 + (size_t)e * FF * DM + (size_t)bk * DM + nbase + bn;

    float acc[2][8][4];
#pragma unroll
    for (int i = 0; i < 2; i++)
#pragma unroll
        for (int j = 0; j < 8; j++)
#pragma unroll
            for (int k = 0; k < 4; k++) acc[i][j][k] = 0.f;

    float4 ra[4], rb[4];
#pragma unroll
    for (int j = 0; j < 4; j++) {
        ra[j] = *reinterpret_cast<const float4*>(arow + j * 4);
        rb[j] = *reinterpret_cast<const float4*>(wrow + j * 4);
    }

    int buf = 0;
    for (int kt = 0; kt < FF; kt += 32) {
        float* As = sm + HDR + buf * STAGEF;
        float* Bs = As + 128 * SA;
#pragma unroll
        for (int j = 0; j < 4; j++) {
            *reinterpret_cast<float4*>(&As[am * SA + ak + j * 4]) = ra[j];
            *reinterpret_cast<float4*>(&Bs[bk * SB + bn + j * 4]) = rb[j];
        }
        __syncthreads();
        if (kt + 32 < FF) {
#pragma unroll
            for (int j = 0; j < 4; j++) {
                ra[j] = *reinterpret_cast<const float4*>(arow + kt + 32 + j * 4);
                rb[j] = *reinterpret_cast<const float4*>(wrow + (size_t)(kt + 32) * DM + j * 4);
            }
        }
        compute_stage(As, Bs, wm, wn, lid, acc);
        buf ^= 1;
    }

    // epilogue: bias + gate-weighted scatter (validated R7)
    const int qr = lid >> 2, c2 = (lid & 3) * 2;
#pragma unroll
    for (int mf = 0; mf < 2; mf++)
#pragma unroll
        for (int half = 0; half < 2; half++) {
            int mloc = wm + mf * 16 + qr + half * 8;
            int m = mbase + mloc;
            if (m < cnt) {
                int   tok = stok[mloc];
                float wv  = swt[mloc];
                float* orow = out + (size_t)tok * DM + nbase;
#pragma unroll
                for (int g = 0; g < 8; g++) {
                    int cl = wn + g * 8 + c2;
                    atomicAdd(&orow[cl],     wv * (acc[mf][g][half * 2]     + sbias[cl]));
                    atomicAdd(&orow[cl + 1], wv * (acc[mf][g][half * 2 + 1] + sbias[cl + 1]));
                }
            }
        }
}

// ---------------------------------------------------------------
extern "C" void kernel_launch(void* const* d_in, const int* in_sizes, int n_in,
                              void* d_out, int out_size) {
    const float* x  = (const float*)d_in[0];
    const float* Wg = (const float*)d_in[1];
    const float* bg = (const float*)d_in[2];
    const float* W1 = (const float*)d_in[3];
    const float* b1 = (const float*)d_in[4];
    const float* W2 = (const float*)d_in[5];
    const float* b2 = (const float*)d_in[6];
    float* out = (float*)d_out;

    cudaFuncSetAttribute(ffn1_hmma, cudaFuncAttributeMaxDynamicSharedMemorySize, SMEM_BYTES);
    cudaFuncSetAttribute(ffn2_hmma, cudaFuncAttributeMaxDynamicSharedMemorySize, SMEM_BYTES);

    zero_kernel<<<NT * DM / 4 / 256, 256>>>(out);
    gate_kernel<<<1024, 256>>>(x, Wg, bg);
    offsets_kernel<<<1, 32>>>();
    ffn1_hmma<<<dim3(FF / 128, NT / 128, NE), 256, SMEM_BYTES>>>(x, W1, b1);
    ffn2_hmma<<<dim3(DM / 128, NT / 128, NE), 256, SMEM_BYTES>>>(W2, b2, out);
}